// round 16
// baseline (speedup 1.0000x reference)
#include <cuda_runtime.h>
#include <math.h>

#define NROWS 65536
#define KCODES 4096
#define DDIM 256

typedef unsigned long long ull;

// ---- scratch (static device globals; no allocation) ----
// __align__(16) is load-bearing: these are read with 16B vector loads.
__device__ __align__(16) float  g_wsq[KCODES];
__device__ __align__(16) float  g_zsq[NROWS];
__device__ __align__(16) float  g_wnew[KCODES * DDIM];  // aligned copy of new_weight
__device__ int    g_idx[NROWS];
__device__ int    g_cnt[KCODES];
__device__ double g_loss;

// ---- f32x2 packed FMA helpers (sm_100+) ----
__device__ __forceinline__ ull pack2(float lo, float hi) {
    ull r; asm("mov.b64 %0, {%1,%2};" : "=l"(r) : "f"(lo), "f"(hi)); return r;
}
__device__ __forceinline__ void unpack2(float& lo, float& hi, ull v) {
    asm("mov.b64 {%0,%1}, %2;" : "=f"(lo), "=f"(hi) : "l"(v));
}
__device__ __forceinline__ void fma2(ull& c, ull a, ull b) {
    asm("fma.rn.f32x2 %0, %1, %2, %3;" : "=l"(c) : "l"(a), "l"(b), "l"(c));
}

// ---------------------------------------------------------------------------
// Row squared-norm: one warp per row of a [rows, 256] matrix.
// which==0 -> g_wsq, which==1 -> g_zsq
// ---------------------------------------------------------------------------
__global__ void rownorm_kernel(const float* __restrict__ x, int rows, int which) {
    int row = blockIdx.x * 8 + (threadIdx.x >> 5);
    if (row >= rows) return;
    int lane = threadIdx.x & 31;
    const float4* r4 = (const float4*)(x + (size_t)row * DDIM);
    float4 a = r4[lane];
    float4 b = r4[lane + 32];
    float s = a.x * a.x + a.y * a.y + a.z * a.z + a.w * a.w
            + b.x * b.x + b.y * b.y + b.z * b.z + b.w * b.w;
#pragma unroll
    for (int o = 16; o > 0; o >>= 1) s += __shfl_xor_sync(0xffffffffu, s, o);
    if (lane == 0) { if (which) g_zsq[row] = s; else g_wsq[row] = s; }
}

// ---------------------------------------------------------------------------
// Init: new_ema_w = 0.99 * ema_w (scatter target), zero counters.
// grid 4096 x 256 = exactly K*D threads. Scalar stores (out_emaw may be
// only 8B aligned within d_out).
// ---------------------------------------------------------------------------
__global__ void init_kernel(const float* __restrict__ ema_w, float* __restrict__ out_emaw) {
    int i = blockIdx.x * 256 + threadIdx.x;
    out_emaw[i] = 0.99f * ema_w[i];
    if (i < KCODES) g_cnt[i] = 0;
    if (i == 0) g_loss = 0.0;
}

// ---------------------------------------------------------------------------
// Argmin GEMM: per block 128 rows x all 4096 codes, D=256 reduction.
// 256 threads, 8x8 micro-tile per thread, f32x2 packed FMAs pairing rows.
// s(n,k) = (zsq[n] + wsq[k]) - 2*dot(z_n, w_k)  (exactly the ref formula).
// Tie-break: smallest k, via packed (ordered_float<<32 | k) atomicMin.
// ---------------------------------------------------------------------------
__global__ void __launch_bounds__(256, 2) argmin_kernel(
    const float* __restrict__ z, const float* __restrict__ w,
    float* __restrict__ out_idx)
{
    __shared__ __align__(16) float Zs[2][8][128];
    __shared__ __align__(16) float Ws[2][8][128];
    __shared__ ull rbest[128];

    const int tid  = threadIdx.x;
    const int tcol = tid & 15;
    const int trow = tid >> 4;
    const int rb   = trow * 8;          // local row base (8 rows)
    const int cb   = tcol * 8;          // local col base (8 cols)
    const int lrow = tid & 127;         // gmem-load row within tile
    const int lds4 = (tid >> 7) << 2;   // gmem-load d offset (0 or 4)
    const size_t blockRow = (size_t)blockIdx.x * 128;

    if (tid < 128) rbest[tid] = 0xFFFFFFFFFFFFFFFFull;

    float zrq[8];
#pragma unroll
    for (int i = 0; i < 8; i++) zrq[i] = g_zsq[blockRow + rb + i];

    float bestv[8]; int besti[8];
#pragma unroll
    for (int i = 0; i < 8; i++) { bestv[i] = 3.402823466e38f; besti[i] = 0; }

    const float* zbase = z + (blockRow + (size_t)lrow) * DDIM + lds4;

    for (int kt = 0; kt < KCODES; kt += 128) {
        const float* wbase = w + ((size_t)kt + lrow) * DDIM + lds4;

        ull acc[4][8];
#pragma unroll
        for (int p = 0; p < 4; p++)
#pragma unroll
            for (int c = 0; c < 8; c++) acc[p][c] = 0ull;

        // prologue: load first 8-wide D chunk into buffer 0
        {
            float4 zv = *(const float4*)(zbase);
            float4 wv = *(const float4*)(wbase);
            Zs[0][lds4 + 0][lrow] = zv.x; Zs[0][lds4 + 1][lrow] = zv.y;
            Zs[0][lds4 + 2][lrow] = zv.z; Zs[0][lds4 + 3][lrow] = zv.w;
            Ws[0][lds4 + 0][lrow] = wv.x; Ws[0][lds4 + 1][lrow] = wv.y;
            Ws[0][lds4 + 2][lrow] = wv.z; Ws[0][lds4 + 3][lrow] = wv.w;
        }
        __syncthreads();

        int buf = 0;
#pragma unroll 1
        for (int dc = 0; dc < DDIM; dc += 8) {
            float4 zn, wn;
            const bool more = (dc + 8) < DDIM;
            if (more) {
                zn = *(const float4*)(zbase + dc + 8);
                wn = *(const float4*)(wbase + dc + 8);
            }
#pragma unroll
            for (int d = 0; d < 8; d++) {
                const float* zp = &Zs[buf][d][rb];
                ulonglong2 A0 = *(const ulonglong2*)(zp);      // rows rb..rb+3 as 2 pairs
                ulonglong2 A1 = *(const ulonglong2*)(zp + 4);  // rows rb+4..rb+7
                float bv[8];
                *(float4*)&bv[0] = *(const float4*)&Ws[buf][d][cb];
                *(float4*)&bv[4] = *(const float4*)&Ws[buf][d][cb + 4];
#pragma unroll
                for (int c = 0; c < 8; c++) {
                    ull bd = pack2(bv[c], bv[c]);
                    fma2(acc[0][c], A0.x, bd);
                    fma2(acc[1][c], A0.y, bd);
                    fma2(acc[2][c], A1.x, bd);
                    fma2(acc[3][c], A1.y, bd);
                }
            }
            if (more) {
                int nb = buf ^ 1;
                Zs[nb][lds4 + 0][lrow] = zn.x; Zs[nb][lds4 + 1][lrow] = zn.y;
                Zs[nb][lds4 + 2][lrow] = zn.z; Zs[nb][lds4 + 3][lrow] = zn.w;
                Ws[nb][lds4 + 0][lrow] = wn.x; Ws[nb][lds4 + 1][lrow] = wn.y;
                Ws[nb][lds4 + 2][lrow] = wn.z; Ws[nb][lds4 + 3][lrow] = wn.w;
                __syncthreads();
                buf = nb;
            }
        }

        // tile epilogue: fold dot products into running argmin
        float qs[8];
        *(float4*)&qs[0] = *(const float4*)&g_wsq[kt + cb];
        *(float4*)&qs[4] = *(const float4*)&g_wsq[kt + cb + 4];
#pragma unroll
        for (int p = 0; p < 4; p++) {
#pragma unroll
            for (int c = 0; c < 8; c++) {
                float lo, hi;
                unpack2(lo, hi, acc[p][c]);
                const int col = kt + cb + c;
                const int r0 = 2 * p, r1 = 2 * p + 1;
                float s0 = fmaf(-2.0f, lo, zrq[r0] + qs[c]);
                float s1 = fmaf(-2.0f, hi, zrq[r1] + qs[c]);
                if (s0 < bestv[r0]) { bestv[r0] = s0; besti[r0] = col; }
                if (s1 < bestv[r1]) { bestv[r1] = s1; besti[r1] = col; }
            }
        }
        __syncthreads();
    }

    // block-level reduction across the 16 thread-columns per row
#pragma unroll
    for (int i = 0; i < 8; i++) {
        unsigned u = __float_as_uint(bestv[i]);
        u = (u & 0x80000000u) ? ~u : (u | 0x80000000u);   // order-preserving map
        ull key = ((ull)u << 32) | (unsigned)besti[i];
        atomicMin(&rbest[rb + i], key);
    }
    __syncthreads();
    if (tid < 128) {
        ull key = rbest[tid];
        int k = (int)(unsigned)(key & 0xFFFFFFFFull);
        g_idx[blockRow + tid]  = k;
        out_idx[blockRow + tid] = (float)k;
    }
}

// ---------------------------------------------------------------------------
// Scatter: counts + 0.01*z into new_ema_w rows (already holding 0.99*ema_w).
// One warp per z row. Scalar atomics (out_emaw only 8B aligned — fine).
// ---------------------------------------------------------------------------
__global__ void scatter_kernel(const float* __restrict__ z, float* __restrict__ out_emaw) {
    int row  = blockIdx.x * 8 + (threadIdx.x >> 5);
    int lane = threadIdx.x & 31;
    int k = g_idx[row];
    if (lane == 0) atomicAdd(&g_cnt[k], 1);
    const float4* zr = (const float4*)(z + (size_t)row * DDIM);
    float* er = out_emaw + (size_t)k * DDIM;
#pragma unroll
    for (int j = 0; j < 2; j++) {
        int c = lane + j * 32;
        float4 v = zr[c];
        atomicAdd(er + c * 4 + 0, 0.01f * v.x);
        atomicAdd(er + c * 4 + 1, 0.01f * v.y);
        atomicAdd(er + c * 4 + 2, 0.01f * v.z);
        atomicAdd(er + c * 4 + 3, 0.01f * v.w);
    }
}

// ---------------------------------------------------------------------------
// Cluster-size smoothing + perplexity. Single block, 1024 threads x 4 codes.
// ---------------------------------------------------------------------------
__global__ void normalize_kernel(const float* __restrict__ ema_cs,
                                 float* __restrict__ out_cs,
                                 float* __restrict__ out_perp)
{
    const int t = threadIdx.x;
    float csr[4];
    double nsum = 0.0, psum = 0.0;
#pragma unroll
    for (int j = 0; j < 4; j++) {
        int k = t * 4 + j;
        int c = g_cnt[k];
        float cs = 0.99f * ema_cs[k] + 0.01f * (float)c;
        csr[j] = cs;
        nsum += (double)cs;
        float p = (float)c * (1.0f / 65536.0f);
        psum += (double)(p * logf(p + 1e-10f));
    }
#pragma unroll
    for (int o = 16; o > 0; o >>= 1) {
        nsum += __shfl_xor_sync(0xffffffffu, nsum, o);
        psum += __shfl_xor_sync(0xffffffffu, psum, o);
    }
    __shared__ double sn[32], sp[32];
    __shared__ float s_n;
    int warp = t >> 5, lane = t & 31;
    if (lane == 0) { sn[warp] = nsum; sp[warp] = psum; }
    __syncthreads();
    if (t == 0) {
        double a = 0.0, b = 0.0;
        for (int i = 0; i < 32; i++) { a += sn[i]; b += sp[i]; }
        s_n = (float)a;
        out_perp[0] = expf((float)(-b));
    }
    __syncthreads();
    float n = s_n;
    float denom = n + 4096.0f * 1e-5f;
#pragma unroll
    for (int j = 0; j < 4; j++) {
        int k = t * 4 + j;
        out_cs[k] = (csr[j] + 1e-5f) / denom * n;
    }
}

// ---------------------------------------------------------------------------
// new_weight = new_ema_w / cs[:,None].
// Writes BOTH the (possibly 8B-aligned) output slot with scalar stores AND the
// 16B-aligned g_wnew scratch that zq_loss_kernel gathers from with float4.
// ---------------------------------------------------------------------------
__global__ void newweight_kernel(const float* __restrict__ emaw,
                                 const float* __restrict__ cs,
                                 float* __restrict__ out_w)
{
    int i = blockIdx.x * 256 + threadIdx.x;
    float v = emaw[i] / cs[i >> 8];
    out_w[i]  = v;
    g_wnew[i] = v;
}

// ---------------------------------------------------------------------------
// z_q gather (straight-through: z + (w - z)) + loss accumulation.
// One warp per row. Reads codebook from aligned g_wnew scratch.
// ---------------------------------------------------------------------------
__global__ void zq_loss_kernel(const float* __restrict__ z,
                               float* __restrict__ out_zq)
{
    int row  = blockIdx.x * 8 + (threadIdx.x >> 5);
    int lane = threadIdx.x & 31;
    int k = g_idx[row];
    const float4* zr = (const float4*)(z + (size_t)row * DDIM);
    const float4* wr = (const float4*)(g_wnew + (size_t)k * DDIM);
    float4* qr = (float4*)(out_zq + (size_t)row * DDIM);
    float acc = 0.0f;
#pragma unroll
    for (int j = 0; j < 2; j++) {
        int c = lane + j * 32;
        float4 zv = zr[c], wv = wr[c];
        float dx = wv.x - zv.x, dy = wv.y - zv.y, dz = wv.z - zv.z, dw = wv.w - zv.w;
        float4 q;
        q.x = zv.x + dx; q.y = zv.y + dy; q.z = zv.z + dz; q.w = zv.w + dw;
        qr[c] = q;
        acc += dx * dx + dy * dy + dz * dz + dw * dw;
    }
#pragma unroll
    for (int o = 16; o > 0; o >>= 1) acc += __shfl_xor_sync(0xffffffffu, acc, o);
    __shared__ float wsum[8];
    if (lane == 0) wsum[threadIdx.x >> 5] = acc;
    __syncthreads();
    if (threadIdx.x == 0) {
        float s = 0.0f;
#pragma unroll
        for (int i = 0; i < 8; i++) s += wsum[i];
        atomicAdd(&g_loss, (double)s);
    }
}

__global__ void finalize_kernel(float* __restrict__ out_loss) {
    float m = (float)(g_loss * (1.0 / (65536.0 * 256.0)));
    out_loss[0] = m + 0.25f * m;   // mean + BETA*mean (identical squares)
}

// ---------------------------------------------------------------------------
// launch
// ---------------------------------------------------------------------------
extern "C" void kernel_launch(void* const* d_in, const int* in_sizes, int n_in,
                              void* d_out, int out_size)
{
    const float* z      = (const float*)d_in[0];   // [65536,256]
    const float* w      = (const float*)d_in[1];   // [4096,256]
    const float* ema_w  = (const float*)d_in[2];   // [4096,256]
    const float* ema_cs = (const float*)d_in[3];   // [4096]

    float* out      = (float*)d_out;
    float* out_zq   = out;                         // 16,777,216
    float* out_idx  = out_zq + 16777216;           //     65,536
    float* out_loss = out_idx + 65536;             //          1
    float* out_perp = out_loss + 1;                //          1
    float* out_cs   = out_perp + 1;                //      4,096
    float* out_emaw = out_cs + 4096;               //  1,048,576
    float* out_w    = out_emaw + 1048576;          //  1,048,576

    rownorm_kernel<<<512, 256>>>(w, KCODES, 0);
    rownorm_kernel<<<8192, 256>>>(z, NROWS, 1);
    init_kernel<<<4096, 256>>>(ema_w, out_emaw);
    argmin_kernel<<<512, 256>>>(z, w, out_idx);
    scatter_kernel<<<8192, 256>>>(z, out_emaw);
    normalize_kernel<<<1, 1024>>>(ema_cs, out_cs, out_perp);
    newweight_kernel<<<4096, 256>>>(out_emaw, out_cs, out_w);
    zq_loss_kernel<<<8192, 256>>>(z, out_zq);
    finalize_kernel<<<1, 1>>>(out_loss);
}

// round 17
// speedup vs baseline: 1.0013x; 1.0013x over previous
#include <cuda_runtime.h>
#include <math.h>

#define NROWS 65536
#define KCODES 4096
#define DDIM 256

typedef unsigned long long ull;

// ---- scratch (static device globals; no allocation) ----
// __align__(16) is load-bearing: these are read with 16B vector loads.
__device__ __align__(16) float  g_wsq[KCODES];
__device__ __align__(16) float  g_zsq[NROWS];
__device__ __align__(16) float  g_wnew[KCODES * DDIM];  // aligned copy of new_weight
__device__ int    g_idx[NROWS];
__device__ int    g_cnt[KCODES];
__device__ double g_loss;

// ---- f32x2 packed FMA helpers (sm_100+) ----
__device__ __forceinline__ ull pack2(float lo, float hi) {
    ull r; asm("mov.b64 %0, {%1,%2};" : "=l"(r) : "f"(lo), "f"(hi)); return r;
}
__device__ __forceinline__ void unpack2(float& lo, float& hi, ull v) {
    asm("mov.b64 {%0,%1}, %2;" : "=f"(lo), "=f"(hi) : "l"(v));
}
__device__ __forceinline__ void fma2(ull& c, ull a, ull b) {
    asm("fma.rn.f32x2 %0, %1, %2, %3;" : "=l"(c) : "l"(a), "l"(b), "l"(c));
}

// ---------------------------------------------------------------------------
// Row squared-norm: one warp per row of a [rows, 256] matrix.
// which==0 -> g_wsq, which==1 -> g_zsq
// ---------------------------------------------------------------------------
__global__ void rownorm_kernel(const float* __restrict__ x, int rows, int which) {
    int row = blockIdx.x * 8 + (threadIdx.x >> 5);
    if (row >= rows) return;
    int lane = threadIdx.x & 31;
    const float4* r4 = (const float4*)(x + (size_t)row * DDIM);
    float4 a = r4[lane];
    float4 b = r4[lane + 32];
    float s = a.x * a.x + a.y * a.y + a.z * a.z + a.w * a.w
            + b.x * b.x + b.y * b.y + b.z * b.z + b.w * b.w;
#pragma unroll
    for (int o = 16; o > 0; o >>= 1) s += __shfl_xor_sync(0xffffffffu, s, o);
    if (lane == 0) { if (which) g_zsq[row] = s; else g_wsq[row] = s; }
}

// ---------------------------------------------------------------------------
// Init: new_ema_w = 0.99 * ema_w (scatter target), zero counters.
// grid 4096 x 256 = exactly K*D threads. Scalar stores (out_emaw may be
// only 8B aligned within d_out).
// ---------------------------------------------------------------------------
__global__ void init_kernel(const float* __restrict__ ema_w, float* __restrict__ out_emaw) {
    int i = blockIdx.x * 256 + threadIdx.x;
    out_emaw[i] = 0.99f * ema_w[i];
    if (i < KCODES) g_cnt[i] = 0;
    if (i == 0) g_loss = 0.0;
}

// ---------------------------------------------------------------------------
// Argmin GEMM: per block 128 rows x all 4096 codes, D=256 reduction.
// 256 threads, 8x8 micro-tile per thread, f32x2 packed FMAs pairing rows.
// s(n,k) = (zsq[n] + wsq[k]) - 2*dot(z_n, w_k)  (exactly the ref formula).
// Tie-break: smallest k, via packed (ordered_float<<32 | k) atomicMin.
// ---------------------------------------------------------------------------
__global__ void __launch_bounds__(256, 2) argmin_kernel(
    const float* __restrict__ z, const float* __restrict__ w,
    float* __restrict__ out_idx)
{
    __shared__ __align__(16) float Zs[2][8][128];
    __shared__ __align__(16) float Ws[2][8][128];
    __shared__ ull rbest[128];

    const int tid  = threadIdx.x;
    const int tcol = tid & 15;
    const int trow = tid >> 4;
    const int rb   = trow * 8;          // local row base (8 rows)
    const int cb   = tcol * 8;          // local col base (8 cols)
    const int lrow = tid & 127;         // gmem-load row within tile
    const int lds4 = (tid >> 7) << 2;   // gmem-load d offset (0 or 4)
    const size_t blockRow = (size_t)blockIdx.x * 128;

    if (tid < 128) rbest[tid] = 0xFFFFFFFFFFFFFFFFull;

    float zrq[8];
#pragma unroll
    for (int i = 0; i < 8; i++) zrq[i] = g_zsq[blockRow + rb + i];

    float bestv[8]; int besti[8];
#pragma unroll
    for (int i = 0; i < 8; i++) { bestv[i] = 3.402823466e38f; besti[i] = 0; }

    const float* zbase = z + (blockRow + (size_t)lrow) * DDIM + lds4;

    for (int kt = 0; kt < KCODES; kt += 128) {
        const float* wbase = w + ((size_t)kt + lrow) * DDIM + lds4;

        ull acc[4][8];
#pragma unroll
        for (int p = 0; p < 4; p++)
#pragma unroll
            for (int c = 0; c < 8; c++) acc[p][c] = 0ull;

        // prologue: load first 8-wide D chunk into buffer 0
        {
            float4 zv = *(const float4*)(zbase);
            float4 wv = *(const float4*)(wbase);
            Zs[0][lds4 + 0][lrow] = zv.x; Zs[0][lds4 + 1][lrow] = zv.y;
            Zs[0][lds4 + 2][lrow] = zv.z; Zs[0][lds4 + 3][lrow] = zv.w;
            Ws[0][lds4 + 0][lrow] = wv.x; Ws[0][lds4 + 1][lrow] = wv.y;
            Ws[0][lds4 + 2][lrow] = wv.z; Ws[0][lds4 + 3][lrow] = wv.w;
        }
        __syncthreads();

        int buf = 0;
#pragma unroll 1
        for (int dc = 0; dc < DDIM; dc += 8) {
            float4 zn, wn;
            const bool more = (dc + 8) < DDIM;
            if (more) {
                zn = *(const float4*)(zbase + dc + 8);
                wn = *(const float4*)(wbase + dc + 8);
            }
#pragma unroll
            for (int d = 0; d < 8; d++) {
                const float* zp = &Zs[buf][d][rb];
                ulonglong2 A0 = *(const ulonglong2*)(zp);      // rows rb..rb+3 as 2 pairs
                ulonglong2 A1 = *(const ulonglong2*)(zp + 4);  // rows rb+4..rb+7
                float bv[8];
                *(float4*)&bv[0] = *(const float4*)&Ws[buf][d][cb];
                *(float4*)&bv[4] = *(const float4*)&Ws[buf][d][cb + 4];
#pragma unroll
                for (int c = 0; c < 8; c++) {
                    ull bd = pack2(bv[c], bv[c]);
                    fma2(acc[0][c], A0.x, bd);
                    fma2(acc[1][c], A0.y, bd);
                    fma2(acc[2][c], A1.x, bd);
                    fma2(acc[3][c], A1.y, bd);
                }
            }
            if (more) {
                int nb = buf ^ 1;
                Zs[nb][lds4 + 0][lrow] = zn.x; Zs[nb][lds4 + 1][lrow] = zn.y;
                Zs[nb][lds4 + 2][lrow] = zn.z; Zs[nb][lds4 + 3][lrow] = zn.w;
                Ws[nb][lds4 + 0][lrow] = wn.x; Ws[nb][lds4 + 1][lrow] = wn.y;
                Ws[nb][lds4 + 2][lrow] = wn.z; Ws[nb][lds4 + 3][lrow] = wn.w;
                __syncthreads();
                buf = nb;
            }
        }

        // tile epilogue: fold dot products into running argmin
        float qs[8];
        *(float4*)&qs[0] = *(const float4*)&g_wsq[kt + cb];
        *(float4*)&qs[4] = *(const float4*)&g_wsq[kt + cb + 4];
#pragma unroll
        for (int p = 0; p < 4; p++) {
#pragma unroll
            for (int c = 0; c < 8; c++) {
                float lo, hi;
                unpack2(lo, hi, acc[p][c]);
                const int col = kt + cb + c;
                const int r0 = 2 * p, r1 = 2 * p + 1;
                float s0 = fmaf(-2.0f, lo, zrq[r0] + qs[c]);
                float s1 = fmaf(-2.0f, hi, zrq[r1] + qs[c]);
                if (s0 < bestv[r0]) { bestv[r0] = s0; besti[r0] = col; }
                if (s1 < bestv[r1]) { bestv[r1] = s1; besti[r1] = col; }
            }
        }
        __syncthreads();
    }

    // block-level reduction across the 16 thread-columns per row
#pragma unroll
    for (int i = 0; i < 8; i++) {
        unsigned u = __float_as_uint(bestv[i]);
        u = (u & 0x80000000u) ? ~u : (u | 0x80000000u);   // order-preserving map
        ull key = ((ull)u << 32) | (unsigned)besti[i];
        atomicMin(&rbest[rb + i], key);
    }
    __syncthreads();
    if (tid < 128) {
        ull key = rbest[tid];
        int k = (int)(unsigned)(key & 0xFFFFFFFFull);
        g_idx[blockRow + tid]  = k;
        out_idx[blockRow + tid] = (float)k;
    }
}

// ---------------------------------------------------------------------------
// Scatter: counts + 0.01*z into new_ema_w rows (already holding 0.99*ema_w).
// One warp per z row. Scalar atomics (out_emaw only 8B aligned — fine).
// ---------------------------------------------------------------------------
__global__ void scatter_kernel(const float* __restrict__ z, float* __restrict__ out_emaw) {
    int row  = blockIdx.x * 8 + (threadIdx.x >> 5);
    int lane = threadIdx.x & 31;
    int k = g_idx[row];
    if (lane == 0) atomicAdd(&g_cnt[k], 1);
    const float4* zr = (const float4*)(z + (size_t)row * DDIM);
    float* er = out_emaw + (size_t)k * DDIM;
#pragma unroll
    for (int j = 0; j < 2; j++) {
        int c = lane + j * 32;
        float4 v = zr[c];
        atomicAdd(er + c * 4 + 0, 0.01f * v.x);
        atomicAdd(er + c * 4 + 1, 0.01f * v.y);
        atomicAdd(er + c * 4 + 2, 0.01f * v.z);
        atomicAdd(er + c * 4 + 3, 0.01f * v.w);
    }
}

// ---------------------------------------------------------------------------
// Cluster-size smoothing + perplexity. Single block, 1024 threads x 4 codes.
// ---------------------------------------------------------------------------
__global__ void normalize_kernel(const float* __restrict__ ema_cs,
                                 float* __restrict__ out_cs,
                                 float* __restrict__ out_perp)
{
    const int t = threadIdx.x;
    float csr[4];
    double nsum = 0.0, psum = 0.0;
#pragma unroll
    for (int j = 0; j < 4; j++) {
        int k = t * 4 + j;
        int c = g_cnt[k];
        float cs = 0.99f * ema_cs[k] + 0.01f * (float)c;
        csr[j] = cs;
        nsum += (double)cs;
        float p = (float)c * (1.0f / 65536.0f);
        psum += (double)(p * logf(p + 1e-10f));
    }
#pragma unroll
    for (int o = 16; o > 0; o >>= 1) {
        nsum += __shfl_xor_sync(0xffffffffu, nsum, o);
        psum += __shfl_xor_sync(0xffffffffu, psum, o);
    }
    __shared__ double sn[32], sp[32];
    __shared__ float s_n;
    int warp = t >> 5, lane = t & 31;
    if (lane == 0) { sn[warp] = nsum; sp[warp] = psum; }
    __syncthreads();
    if (t == 0) {
        double a = 0.0, b = 0.0;
        for (int i = 0; i < 32; i++) { a += sn[i]; b += sp[i]; }
        s_n = (float)a;
        out_perp[0] = expf((float)(-b));
    }
    __syncthreads();
    float n = s_n;
    float denom = n + 4096.0f * 1e-5f;
#pragma unroll
    for (int j = 0; j < 4; j++) {
        int k = t * 4 + j;
        out_cs[k] = (csr[j] + 1e-5f) / denom * n;
    }
}

// ---------------------------------------------------------------------------
// new_weight = new_ema_w / cs[:,None].
// Writes BOTH the (possibly 8B-aligned) output slot with scalar stores AND the
// 16B-aligned g_wnew scratch that zq_loss_kernel gathers from with float4.
// ---------------------------------------------------------------------------
__global__ void newweight_kernel(const float* __restrict__ emaw,
                                 const float* __restrict__ cs,
                                 float* __restrict__ out_w)
{
    int i = blockIdx.x * 256 + threadIdx.x;
    float v = emaw[i] / cs[i >> 8];
    out_w[i]  = v;
    g_wnew[i] = v;
}

// ---------------------------------------------------------------------------
// z_q gather (straight-through: z + (w - z)) + loss accumulation.
// One warp per row. Reads codebook from aligned g_wnew scratch.
// ---------------------------------------------------------------------------
__global__ void zq_loss_kernel(const float* __restrict__ z,
                               float* __restrict__ out_zq)
{
    int row  = blockIdx.x * 8 + (threadIdx.x >> 5);
    int lane = threadIdx.x & 31;
    int k = g_idx[row];
    const float4* zr = (const float4*)(z + (size_t)row * DDIM);
    const float4* wr = (const float4*)(g_wnew + (size_t)k * DDIM);
    float4* qr = (float4*)(out_zq + (size_t)row * DDIM);
    float acc = 0.0f;
#pragma unroll
    for (int j = 0; j < 2; j++) {
        int c = lane + j * 32;
        float4 zv = zr[c], wv = wr[c];
        float dx = wv.x - zv.x, dy = wv.y - zv.y, dz = wv.z - zv.z, dw = wv.w - zv.w;
        float4 q;
        q.x = zv.x + dx; q.y = zv.y + dy; q.z = zv.z + dz; q.w = zv.w + dw;
        qr[c] = q;
        acc += dx * dx + dy * dy + dz * dz + dw * dw;
    }
#pragma unroll
    for (int o = 16; o > 0; o >>= 1) acc += __shfl_xor_sync(0xffffffffu, acc, o);
    __shared__ float wsum[8];
    if (lane == 0) wsum[threadIdx.x >> 5] = acc;
    __syncthreads();
    if (threadIdx.x == 0) {
        float s = 0.0f;
#pragma unroll
        for (int i = 0; i < 8; i++) s += wsum[i];
        atomicAdd(&g_loss, (double)s);
    }
}

__global__ void finalize_kernel(float* __restrict__ out_loss) {
    float m = (float)(g_loss * (1.0 / (65536.0 * 256.0)));
    out_loss[0] = m + 0.25f * m;   // mean + BETA*mean (identical squares)
}

// ---------------------------------------------------------------------------
// launch
// ---------------------------------------------------------------------------
extern "C" void kernel_launch(void* const* d_in, const int* in_sizes, int n_in,
                              void* d_out, int out_size)
{
    const float* z      = (const float*)d_in[0];   // [65536,256]
    const float* w      = (const float*)d_in[1];   // [4096,256]
    const float* ema_w  = (const float*)d_in[2];   // [4096,256]
    const float* ema_cs = (const float*)d_in[3];   // [4096]

    float* out      = (float*)d_out;
    float* out_zq   = out;                         // 16,777,216
    float* out_idx  = out_zq + 16777216;           //     65,536
    float* out_loss = out_idx + 65536;             //          1
    float* out_perp = out_loss + 1;                //          1
    float* out_cs   = out_perp + 1;                //      4,096
    float* out_emaw = out_cs + 4096;               //  1,048,576
    float* out_w    = out_emaw + 1048576;          //  1,048,576

    rownorm_kernel<<<512, 256>>>(w, KCODES, 0);
    rownorm_kernel<<<8192, 256>>>(z, NROWS, 1);
    init_kernel<<<4096, 256>>>(ema_w, out_emaw);
    argmin_kernel<<<512, 256>>>(z, w, out_idx);
    scatter_kernel<<<8192, 256>>>(z, out_emaw);
    normalize_kernel<<<1, 1024>>>(ema_cs, out_cs, out_perp);
    newweight_kernel<<<4096, 256>>>(out_emaw, out_cs, out_w);
    zq_loss_kernel<<<8192, 256>>>(z, out_zq);
    finalize_kernel<<<1, 1>>>(out_loss);
}